// round 1
// baseline (speedup 1.0000x reference)
#include <cuda_runtime.h>
#include <cuda_bf16.h>

#define BB 256
#define TT 256
#define EMB 384
#define HH 6
#define DD 64

// Scratch (allocation-free rule: __device__ globals)
__device__ float g_q[BB * HH * TT * DD];
__device__ float g_k[BB * HH * TT * DD];
__device__ float g_v[BB * HH * TT * DD];
__device__ float g_att[BB * TT * HH * DD];

// ---------------------------------------------------------------------------
// Kernel 1: QKV projection. out[b,h,t,d] = sum_e x[b,t,e] * w[h,e,d]
// grid: (T/64, B*H, 3), block: 256. 64x64 tile, K-chunk 32.
// ---------------------------------------------------------------------------
__global__ __launch_bounds__(256) void qkv_kernel(
    const float* __restrict__ x,
    const float* __restrict__ wq,
    const float* __restrict__ wk,
    const float* __restrict__ wv)
{
    __shared__ float xs[64][33];
    __shared__ float ws[32][64];

    const int ttile = blockIdx.x;           // 0..3
    const int bh    = blockIdx.y;           // b*H + h
    const int z     = blockIdx.z;           // 0=q 1=k 2=v
    const int b     = bh / HH;
    const int h     = bh % HH;

    const float* w  = (z == 0 ? wq : (z == 1 ? wk : wv)) + h * EMB * DD;
    float* out      = (z == 0 ? g_q : (z == 1 ? g_k : g_v)) + (bh * TT + ttile * 64) * DD;
    const float* xp = x + (b * TT + ttile * 64) * EMB;

    const int tid = threadIdx.x;
    const int ty  = tid >> 4;    // 0..15 -> rows ty*4..ty*4+3
    const int tx  = tid & 15;    // 0..15 -> cols tx+16*i

    float acc[4][4] = {};

    for (int k0 = 0; k0 < EMB; k0 += 32) {
        __syncthreads();
        // xs: 64 rows x 32 e (coalesced)
        #pragma unroll
        for (int idx = tid; idx < 64 * 32; idx += 256) {
            int r = idx >> 5, c = idx & 31;
            xs[r][c] = xp[r * EMB + k0 + c];
        }
        // ws: 32 e x 64 d (coalesced)
        #pragma unroll
        for (int idx = tid; idx < 32 * 64; idx += 256) {
            int r = idx >> 6, c = idx & 63;
            ws[r][c] = w[(k0 + r) * DD + c];
        }
        __syncthreads();

        #pragma unroll 8
        for (int kk = 0; kk < 32; kk++) {
            float aq[4], bw[4];
            #pragma unroll
            for (int j = 0; j < 4; j++) aq[j] = xs[ty * 4 + j][kk];
            #pragma unroll
            for (int i = 0; i < 4; i++) bw[i] = ws[kk][tx + 16 * i];
            #pragma unroll
            for (int j = 0; j < 4; j++)
                #pragma unroll
                for (int i = 0; i < 4; i++)
                    acc[j][i] += aq[j] * bw[i];
        }
    }

    #pragma unroll
    for (int j = 0; j < 4; j++)
        #pragma unroll
        for (int i = 0; i < 4; i++)
            out[(ty * 4 + j) * DD + tx + 16 * i] = acc[j][i];
}

// ---------------------------------------------------------------------------
// Kernel 2: causal flash attention per (b,h,qtile). Tiles 64x64, D=64.
// Shared: qs (swizzled), kv (K swizzled then V plain), pb (P swizzled) = 48KB.
// ---------------------------------------------------------------------------
__device__ __forceinline__ float redmax16(float v) {
    #pragma unroll
    for (int off = 8; off > 0; off >>= 1)
        v = fmaxf(v, __shfl_xor_sync(0xffffffffu, v, off, 16));
    return v;
}
__device__ __forceinline__ float redsum16(float v) {
    #pragma unroll
    for (int off = 8; off > 0; off >>= 1)
        v += __shfl_xor_sync(0xffffffffu, v, off, 16);
    return v;
}

__global__ __launch_bounds__(256) void attn_kernel()
{
    __shared__ float qs[64][64];   // q, swizzled col: (c + r) & 63, pre-scaled
    __shared__ float kv[64][64];   // K (swizzled) then V (plain) per tile
    __shared__ float pb[64][64];   // P, swizzled

    const int qi = blockIdx.x;     // q tile 0..3
    const int bh = blockIdx.y;     // b*H+h
    const int b  = bh / HH;
    const int h  = bh % HH;

    const float* qp = g_q + (bh * TT + qi * 64) * DD;
    const float* kp = g_k + bh * TT * DD;
    const float* vp = g_v + bh * TT * DD;

    const int tid = threadIdx.x;
    const int ty  = tid >> 4;
    const int tx  = tid & 15;
    const float scale = 0.125f;    // 1/sqrt(64)

    // Load Q (scaled, swizzled)
    #pragma unroll
    for (int idx = tid; idx < 4096; idx += 256) {
        int r = idx >> 6, c = idx & 63;
        qs[r][(c + r) & 63] = qp[r * DD + c] * scale;
    }

    float m[4], l[4], o[4][4];
    #pragma unroll
    for (int j = 0; j < 4; j++) { m[j] = -1e30f; l[j] = 0.0f; }
    #pragma unroll
    for (int j = 0; j < 4; j++)
        #pragma unroll
        for (int i = 0; i < 4; i++) o[j][i] = 0.0f;

    for (int kt = 0; kt <= qi; kt++) {
        __syncthreads();   // prior-iter readers of kv done (also covers Q load)
        // Load K tile swizzled
        #pragma unroll
        for (int idx = tid; idx < 4096; idx += 256) {
            int r = idx >> 6, c = idx & 63;
            kv[r][(c + r) & 63] = kp[(kt * 64 + r) * DD + c];
        }
        __syncthreads();

        // S = Q K^T
        float s[4][4] = {};
        #pragma unroll 4
        for (int dd = 0; dd < 64; dd++) {
            float aq[4], bk[4];
            #pragma unroll
            for (int j = 0; j < 4; j++) {
                int r = ty * 4 + j;
                aq[j] = qs[r][(dd + r) & 63];
            }
            #pragma unroll
            for (int i = 0; i < 4; i++) {
                int c = tx + 16 * i;
                bk[i] = kv[c][(dd + c) & 63];
            }
            #pragma unroll
            for (int j = 0; j < 4; j++)
                #pragma unroll
                for (int i = 0; i < 4; i++)
                    s[j][i] += aq[j] * bk[i];
        }

        // Causal mask on diagonal tile
        if (kt == qi) {
            #pragma unroll
            for (int j = 0; j < 4; j++)
                #pragma unroll
                for (int i = 0; i < 4; i++)
                    if (tx + 16 * i > ty * 4 + j) s[j][i] = -1e30f;
        }

        // Online softmax update
        float alpha[4];
        #pragma unroll
        for (int j = 0; j < 4; j++) {
            float pm = fmaxf(fmaxf(s[j][0], s[j][1]), fmaxf(s[j][2], s[j][3]));
            float rowmax = redmax16(pm);
            float mn = fmaxf(m[j], rowmax);
            alpha[j] = __expf(m[j] - mn);
            m[j] = mn;
            float psum = 0.0f;
            #pragma unroll
            for (int i = 0; i < 4; i++) {
                s[j][i] = __expf(s[j][i] - mn);   // p
                psum += s[j][i];
            }
            l[j] = l[j] * alpha[j] + redsum16(psum);
            #pragma unroll
            for (int i = 0; i < 4; i++) o[j][i] *= alpha[j];
        }

        __syncthreads();   // everyone done reading K from kv

        // Write P (swizzled), load V (plain) into kv
        #pragma unroll
        for (int j = 0; j < 4; j++) {
            int r = ty * 4 + j;
            #pragma unroll
            for (int i = 0; i < 4; i++) {
                int c = tx + 16 * i;
                pb[r][(c + r) & 63] = s[j][i];
            }
        }
        #pragma unroll
        for (int idx = tid; idx < 4096; idx += 256) {
            int r = idx >> 6, c = idx & 63;
            kv[r][c] = vp[(kt * 64 + r) * DD + c];
        }
        __syncthreads();

        // O += P V
        #pragma unroll 4
        for (int jj = 0; jj < 64; jj++) {
            float ap[4], bv[4];
            #pragma unroll
            for (int j = 0; j < 4; j++) {
                int r = ty * 4 + j;
                ap[j] = pb[r][(jj + r) & 63];
            }
            #pragma unroll
            for (int i = 0; i < 4; i++) bv[i] = kv[jj][tx + 16 * i];
            #pragma unroll
            for (int j = 0; j < 4; j++)
                #pragma unroll
                for (int i = 0; i < 4; i++)
                    o[j][i] += ap[j] * bv[i];
        }
    }

    // Epilogue: normalize, write concatenated-heads layout [B,T,H*D]
    float* op = g_att + (b * TT + qi * 64) * (HH * DD) + h * DD;
    #pragma unroll
    for (int j = 0; j < 4; j++) {
        float inv = 1.0f / l[j];
        #pragma unroll
        for (int i = 0; i < 4; i++)
            op[(ty * 4 + j) * (HH * DD) + tx + 16 * i] = o[j][i] * inv;
    }
}

// ---------------------------------------------------------------------------
// Kernel 3: output projection. out[bt,e] = att[bt,:] @ w_proj[:,e] + b_proj[e]
// grid: (EMB/64, B*T/64), block 256.
// ---------------------------------------------------------------------------
__global__ __launch_bounds__(256) void proj_kernel(
    const float* __restrict__ wp,
    const float* __restrict__ bp,
    float* __restrict__ out)
{
    __shared__ float xs[64][33];
    __shared__ float ws[32][64];

    const int ctile = blockIdx.x;   // 0..5
    const int rtile = blockIdx.y;   // 0..1023

    const float* xp = g_att + rtile * 64 * (HH * DD);
    const int tid = threadIdx.x;
    const int ty  = tid >> 4;
    const int tx  = tid & 15;

    float acc[4][4] = {};

    for (int k0 = 0; k0 < HH * DD; k0 += 32) {
        __syncthreads();
        #pragma unroll
        for (int idx = tid; idx < 64 * 32; idx += 256) {
            int r = idx >> 5, c = idx & 31;
            xs[r][c] = xp[r * (HH * DD) + k0 + c];
        }
        #pragma unroll
        for (int idx = tid; idx < 32 * 64; idx += 256) {
            int r = idx >> 6, c = idx & 63;
            ws[r][c] = wp[(k0 + r) * EMB + ctile * 64 + c];
        }
        __syncthreads();

        #pragma unroll 8
        for (int kk = 0; kk < 32; kk++) {
            float aq[4], bw[4];
            #pragma unroll
            for (int j = 0; j < 4; j++) aq[j] = xs[ty * 4 + j][kk];
            #pragma unroll
            for (int i = 0; i < 4; i++) bw[i] = ws[kk][tx + 16 * i];
            #pragma unroll
            for (int j = 0; j < 4; j++)
                #pragma unroll
                for (int i = 0; i < 4; i++)
                    acc[j][i] += aq[j] * bw[i];
        }
    }

    float* op = out + rtile * 64 * EMB + ctile * 64;
    #pragma unroll
    for (int j = 0; j < 4; j++)
        #pragma unroll
        for (int i = 0; i < 4; i++) {
            int c = tx + 16 * i;
            op[(ty * 4 + j) * EMB + c] = acc[j][i] + bp[ctile * 64 + c];
        }
}

// ---------------------------------------------------------------------------
extern "C" void kernel_launch(void* const* d_in, const int* in_sizes, int n_in,
                              void* d_out, int out_size)
{
    const float* x      = (const float*)d_in[0];
    const float* wq     = (const float*)d_in[1];
    const float* wk     = (const float*)d_in[2];
    const float* wv     = (const float*)d_in[3];
    const float* w_proj = (const float*)d_in[4];
    const float* b_proj = (const float*)d_in[5];
    float* out = (float*)d_out;

    dim3 blk(256);
    qkv_kernel<<<dim3(TT / 64, BB * HH, 3), blk>>>(x, wq, wk, wv);
    attn_kernel<<<dim3(TT / 64, BB * HH), blk>>>();
    proj_kernel<<<dim3(EMB / 64, (BB * TT) / 64), blk>>>(w_proj, b_proj, out);
}

// round 3
// speedup vs baseline: 1.9038x; 1.9038x over previous
#include <cuda_runtime.h>
#include <cuda_bf16.h>
#include <cstdint>

#define BB 256
#define TT 256
#define EMB 384
#define HH 6
#define DD 64
#define BT (BB*TT)

// ---------------------------------------------------------------------------
// Scratch (__device__ globals — allocation-free rule)
// ---------------------------------------------------------------------------
__device__ float g_q[BB * HH * TT * DD];
__device__ float g_k[BB * HH * TT * DD];
__device__ float g_v[BB * HH * TT * DD];
__device__ __align__(16) __nv_bfloat16 g_xhi[BT * EMB];
__device__ __align__(16) __nv_bfloat16 g_xlo[BT * EMB];
__device__ __align__(16) __nv_bfloat16 g_wthi[3 * HH * DD * EMB];  // [n=z*384+h*64+d][e]
__device__ __align__(16) __nv_bfloat16 g_wtlo[3 * HH * DD * EMB];
__device__ __align__(16) __nv_bfloat16 g_wphi[EMB * EMB];          // [n][k]
__device__ __align__(16) __nv_bfloat16 g_wplo[EMB * EMB];
__device__ __align__(16) __nv_bfloat16 g_atthi[BT * EMB];
__device__ __align__(16) __nv_bfloat16 g_attlo[BT * EMB];

// ---------------------------------------------------------------------------
// mma.sync / ldmatrix helpers (sm_80-era, works on base compute_103 target)
// ---------------------------------------------------------------------------
__device__ __forceinline__ uint32_t smem_u32(const void* p) {
    uint32_t a;
    asm("{ .reg .u64 t; cvta.to.shared.u64 t, %1; cvt.u32.u64 %0, t; }"
        : "=r"(a) : "l"(p));
    return a;
}

__device__ __forceinline__ void ldm4(uint32_t* r, uint32_t addr) {
    asm volatile("ldmatrix.sync.aligned.m8n8.x4.shared.b16 {%0,%1,%2,%3}, [%4];"
        : "=r"(r[0]), "=r"(r[1]), "=r"(r[2]), "=r"(r[3]) : "r"(addr));
}

__device__ __forceinline__ void mma_bf16(float* c, const uint32_t* a, const uint32_t* b) {
    asm volatile(
        "mma.sync.aligned.m16n8k16.row.col.f32.bf16.bf16.f32 "
        "{%0,%1,%2,%3}, {%4,%5,%6,%7}, {%8,%9}, {%0,%1,%2,%3};"
        : "+f"(c[0]), "+f"(c[1]), "+f"(c[2]), "+f"(c[3])
        : "r"(a[0]), "r"(a[1]), "r"(a[2]), "r"(a[3]), "r"(b[0]), "r"(b[1]));
}

// smem tile layout: 128 rows x 4 units of 16B (row = 64B of bf16 k-chunk).
// unit swizzle u' = u ^ ((r>>1)&3) -> conflict-free ldmatrix and STS.
__device__ __forceinline__ uint32_t swz(uint32_t r, uint32_t u) {
    return (r << 6) + ((u ^ ((r >> 1) & 3u)) << 4);
}

// ---------------------------------------------------------------------------
// Prep kernels: fp32 -> bf16 hi/lo splits (weights also transposed to [n][k])
// ---------------------------------------------------------------------------
__global__ void prep_x(const float* __restrict__ x) {
    int i = blockIdx.x * 256 + threadIdx.x;
    if (i < BT * EMB) {
        float v = x[i];
        __nv_bfloat16 h = __float2bfloat16(v);
        g_xhi[i] = h;
        g_xlo[i] = __float2bfloat16(v - __bfloat162float(h));
    }
}

__global__ void prep_w(const float* __restrict__ wq, const float* __restrict__ wk,
                       const float* __restrict__ wv) {
    int i = blockIdx.x * 256 + threadIdx.x;
    if (i >= 3 * HH * DD * EMB) return;
    int e = i % EMB;
    int d = (i / EMB) % DD;
    int h = (i / (EMB * DD)) % HH;
    int z = i / (EMB * DD * HH);
    const float* w = (z == 0) ? wq : (z == 1) ? wk : wv;
    float v = w[(h * EMB + e) * DD + d];
    __nv_bfloat16 hv = __float2bfloat16(v);
    g_wthi[i] = hv;
    g_wtlo[i] = __float2bfloat16(v - __bfloat162float(hv));
}

__global__ void prep_wp(const float* __restrict__ wp) {
    int i = blockIdx.x * 256 + threadIdx.x;
    if (i >= EMB * EMB) return;
    int k = i % EMB;
    int n = i / EMB;
    float v = wp[k * EMB + n];
    __nv_bfloat16 hv = __float2bfloat16(v);
    g_wphi[i] = hv;
    g_wplo[i] = __float2bfloat16(v - __bfloat162float(hv));
}

// ---------------------------------------------------------------------------
// mma.sync GEMM with 3-term bf16 compensation.
// C[M,N] = A[M,384] * B[384,N], A row-major [m][k], B stored [n][k].
// CTA 128x128, k-chunks of 32, double-buffered smem (4 tiles x 8KB x 2 stages).
// MODE 0: qkv (A = x hi/lo, B = wcat, scatter to g_q/g_k/g_v)
// MODE 1: proj (A = att hi/lo, B = w_proj^T, add bias, write out)
// ---------------------------------------------------------------------------
#define ST_SZ   32768
#define OFF_AHI 0
#define OFF_ALO 8192
#define OFF_BHI 16384
#define OFF_BLO 24576

template<int MODE>
__global__ __launch_bounds__(256) void gemm_tc(const float* __restrict__ bias,
                                               float* __restrict__ outp)
{
    extern __shared__ char sm[];
    const uint32_t sb = smem_u32(sm);

    const char* AhiB = (const char*)(MODE == 0 ? g_xhi : g_atthi);
    const char* AloB = (const char*)(MODE == 0 ? g_xlo : g_attlo);
    const char* BhiB = (const char*)(MODE == 0 ? g_wthi : g_wphi);
    const char* BloB = (const char*)(MODE == 0 ? g_wtlo : g_wplo);

    const int tid  = threadIdx.x;
    const int wid  = tid >> 5;
    const int lane = tid & 31;
    const int m0   = blockIdx.y * 128;
    const int n0   = blockIdx.x * 128;

    // LDG mapping: unit i = tid (rows 0..63) and tid+256 (rows 64..127)
    const int lr = tid >> 2;   // local row
    const int lu = tid & 3;    // 16B unit in row

    // warp tile: 32(m) x 64(n)
    const int wm = (wid >> 1) * 32;
    const int wn = (wid & 1) * 64;
    // ldmatrix lane addressing
    const int a_r  = wm + (lane & 15);
    const int a_u0 = (lane >> 4);
    const int b_r  = wn + ((lane >> 4) & 1) * 8 + (lane & 7);
    const int b_u0 = (lane >> 3) & 1;

    float c[2][8][4];
    #pragma unroll
    for (int mt = 0; mt < 2; mt++)
        #pragma unroll
        for (int nt = 0; nt < 8; nt++)
            #pragma unroll
            for (int q = 0; q < 4; q++) c[mt][nt][q] = 0.0f;

    // ---- prologue: load chunk 0 into stage 0
    {
        #pragma unroll
        for (int j = 0; j < 2; j++) {
            int r = lr + j * 64;
            size_t ga = (size_t)(m0 + r) * 768 + lu * 16;
            size_t gb = (size_t)(n0 + r) * 768 + lu * 16;
            *(uint4*)(sm + OFF_AHI + swz(r, lu)) = *(const uint4*)(AhiB + ga);
            *(uint4*)(sm + OFF_ALO + swz(r, lu)) = *(const uint4*)(AloB + ga);
            *(uint4*)(sm + OFF_BHI + swz(r, lu)) = *(const uint4*)(BhiB + gb);
            *(uint4*)(sm + OFF_BLO + swz(r, lu)) = *(const uint4*)(BloB + gb);
        }
    }
    __syncthreads();

    int stage = 0;
    for (int kc = 0; kc < 12; kc++) {
        // prefetch next chunk into registers
        uint4 v[8];
        if (kc < 11) {
            const int ko = (kc + 1) * 64;
            #pragma unroll
            for (int j = 0; j < 2; j++) {
                int r = lr + j * 64;
                size_t ga = (size_t)(m0 + r) * 768 + ko + lu * 16;
                size_t gb = (size_t)(n0 + r) * 768 + ko + lu * 16;
                v[j * 4 + 0] = *(const uint4*)(AhiB + ga);
                v[j * 4 + 1] = *(const uint4*)(AloB + ga);
                v[j * 4 + 2] = *(const uint4*)(BhiB + gb);
                v[j * 4 + 3] = *(const uint4*)(BloB + gb);
            }
        }

        // compute on current stage
        const uint32_t base = sb + stage * ST_SZ;
        #pragma unroll
        for (int ks = 0; ks < 2; ks++) {
            uint32_t ahi[2][4], alo[2][4], bhi[8][2], blo[8][2];
            #pragma unroll
            for (int mt = 0; mt < 2; mt++) {
                uint32_t r = a_r + mt * 16;
                uint32_t u = ks * 2 + a_u0;
                ldm4(ahi[mt], base + OFF_AHI + swz(r, u));
                ldm4(alo[mt], base + OFF_ALO + swz(r, u));
            }
            #pragma unroll
            for (int p = 0; p < 4; p++) {
                uint32_t r = b_r + p * 16;
                uint32_t u = ks * 2 + b_u0;
                uint32_t t4[4];
                ldm4(t4, base + OFF_BHI + swz(r, u));
                bhi[2 * p][0] = t4[0]; bhi[2 * p][1] = t4[1];
                bhi[2 * p + 1][0] = t4[2]; bhi[2 * p + 1][1] = t4[3];
                ldm4(t4, base + OFF_BLO + swz(r, u));
                blo[2 * p][0] = t4[0]; blo[2 * p][1] = t4[1];
                blo[2 * p + 1][0] = t4[2]; blo[2 * p + 1][1] = t4[3];
            }
            #pragma unroll
            for (int mt = 0; mt < 2; mt++)
                #pragma unroll
                for (int nt = 0; nt < 8; nt++) {
                    mma_bf16(c[mt][nt], ahi[mt], bhi[nt]);
                    mma_bf16(c[mt][nt], alo[mt], bhi[nt]);
                    mma_bf16(c[mt][nt], ahi[mt], blo[nt]);
                }
        }

        // store prefetched chunk to other stage
        if (kc < 11) {
            char* dst = sm + (stage ^ 1) * ST_SZ;
            #pragma unroll
            for (int j = 0; j < 2; j++) {
                int r = lr + j * 64;
                *(uint4*)(dst + OFF_AHI + swz(r, lu)) = v[j * 4 + 0];
                *(uint4*)(dst + OFF_ALO + swz(r, lu)) = v[j * 4 + 1];
                *(uint4*)(dst + OFF_BHI + swz(r, lu)) = v[j * 4 + 2];
                *(uint4*)(dst + OFF_BLO + swz(r, lu)) = v[j * 4 + 3];
            }
        }
        __syncthreads();
        stage ^= 1;
    }

    // ---- epilogue
    const int row0 = lane >> 2;
    const int col0 = (lane & 3) * 2;

    if (MODE == 0) {
        const int z = n0 / 384;          // fixed per CTA (1152 = 3 x 384, 384 % 128 == 0)
        float* zbase = (z == 0) ? g_q : (z == 1) ? g_k : g_v;
        const int nloc = n0 % 384;
        #pragma unroll
        for (int mt = 0; mt < 2; mt++)
            #pragma unroll
            for (int half = 0; half < 2; half++) {
                int m = m0 + wm + mt * 16 + row0 + half * 8;
                int b = m >> 8, t = m & 255;
                #pragma unroll
                for (int nt = 0; nt < 8; nt++) {
                    int n = nloc + wn + nt * 8 + col0;
                    int h = n >> 6, d = n & 63;
                    float2 val = make_float2(c[mt][nt][half * 2], c[mt][nt][half * 2 + 1]);
                    *(float2*)(zbase + (((size_t)b * HH + h) * TT + t) * DD + d) = val;
                }
            }
    } else {
        #pragma unroll
        for (int mt = 0; mt < 2; mt++)
            #pragma unroll
            for (int half = 0; half < 2; half++) {
                int m = m0 + wm + mt * 16 + row0 + half * 8;
                #pragma unroll
                for (int nt = 0; nt < 8; nt++) {
                    int n = n0 + wn + nt * 8 + col0;
                    float2 val = make_float2(c[mt][nt][half * 2] + bias[n],
                                             c[mt][nt][half * 2 + 1] + bias[n + 1]);
                    *(float2*)(outp + (size_t)m * EMB + n) = val;
                }
            }
    }
}

// ---------------------------------------------------------------------------
// Scalar causal flash attention (R1-proven); epilogue writes bf16 hi/lo
// ---------------------------------------------------------------------------
__device__ __forceinline__ float redmax16(float v) {
    #pragma unroll
    for (int off = 8; off > 0; off >>= 1)
        v = fmaxf(v, __shfl_xor_sync(0xffffffffu, v, off, 16));
    return v;
}
__device__ __forceinline__ float redsum16(float v) {
    #pragma unroll
    for (int off = 8; off > 0; off >>= 1)
        v += __shfl_xor_sync(0xffffffffu, v, off, 16);
    return v;
}

__global__ __launch_bounds__(256) void attn_kernel()
{
    __shared__ float qs[64][64];
    __shared__ float kv[64][64];
    __shared__ float pb[64][64];

    const int qi = blockIdx.x;
    const int bh = blockIdx.y;
    const int b  = bh / HH;
    const int h  = bh % HH;

    const float* qp = g_q + ((size_t)bh * TT + qi * 64) * DD;
    const float* kp = g_k + (size_t)bh * TT * DD;
    const float* vp = g_v + (size_t)bh * TT * DD;

    const int tid = threadIdx.x;
    const int ty  = tid >> 4;
    const int tx  = tid & 15;
    const float scale = 0.125f;

    #pragma unroll
    for (int idx = tid; idx < 4096; idx += 256) {
        int r = idx >> 6, c = idx & 63;
        qs[r][(c + r) & 63] = qp[r * DD + c] * scale;
    }

    float m[4], l[4], o[4][4];
    #pragma unroll
    for (int j = 0; j < 4; j++) { m[j] = -1e30f; l[j] = 0.0f; }
    #pragma unroll
    for (int j = 0; j < 4; j++)
        #pragma unroll
        for (int i = 0; i < 4; i++) o[j][i] = 0.0f;

    for (int kt = 0; kt <= qi; kt++) {
        __syncthreads();
        #pragma unroll
        for (int idx = tid; idx < 4096; idx += 256) {
            int r = idx >> 6, c = idx & 63;
            kv[r][(c + r) & 63] = kp[(kt * 64 + r) * DD + c];
        }
        __syncthreads();

        float s[4][4] = {};
        #pragma unroll 4
        for (int dd = 0; dd < 64; dd++) {
            float aq[4], bk[4];
            #pragma unroll
            for (int j = 0; j < 4; j++) {
                int r = ty * 4 + j;
                aq[j] = qs[r][(dd + r) & 63];
            }
            #pragma unroll
            for (int i = 0; i < 4; i++) {
                int cc = tx + 16 * i;
                bk[i] = kv[cc][(dd + cc) & 63];
            }
            #pragma unroll
            for (int j = 0; j < 4; j++)
                #pragma unroll
                for (int i = 0; i < 4; i++)
                    s[j][i] += aq[j] * bk[i];
        }

        if (kt == qi) {
            #pragma unroll
            for (int j = 0; j < 4; j++)
                #pragma unroll
                for (int i = 0; i < 4; i++)
                    if (tx + 16 * i > ty * 4 + j) s[j][i] = -1e30f;
        }

        float alpha[4];
        #pragma unroll
        for (int j = 0; j < 4; j++) {
            float pm = fmaxf(fmaxf(s[j][0], s[j][1]), fmaxf(s[j][2], s[j][3]));
            float rowmax = redmax16(pm);
            float mn = fmaxf(m[j], rowmax);
            alpha[j] = __expf(m[j] - mn);
            m[j] = mn;
            float psum = 0.0f;
            #pragma unroll
            for (int i = 0; i < 4; i++) {
                s[j][i] = __expf(s[j][i] - mn);
                psum += s[j][i];
            }
            l[j] = l[j] * alpha[j] + redsum16(psum);
            #pragma unroll
            for (int i = 0; i < 4; i++) o[j][i] *= alpha[j];
        }

        __syncthreads();

        #pragma unroll
        for (int j = 0; j < 4; j++) {
            int r = ty * 4 + j;
            #pragma unroll
            for (int i = 0; i < 4; i++) {
                int cc = tx + 16 * i;
                pb[r][(cc + r) & 63] = s[j][i];
            }
        }
        #pragma unroll
        for (int idx = tid; idx < 4096; idx += 256) {
            int r = idx >> 6, cc = idx & 63;
            kv[r][cc] = vp[(kt * 64 + r) * DD + cc];
        }
        __syncthreads();

        #pragma unroll 4
        for (int jj = 0; jj < 64; jj++) {
            float ap[4], bv[4];
            #pragma unroll
            for (int j = 0; j < 4; j++) {
                int r = ty * 4 + j;
                ap[j] = pb[r][(jj + r) & 63];
            }
            #pragma unroll
            for (int i = 0; i < 4; i++) bv[i] = kv[jj][tx + 16 * i];
            #pragma unroll
            for (int j = 0; j < 4; j++)
                #pragma unroll
                for (int i = 0; i < 4; i++)
                    o[j][i] += ap[j] * bv[i];
        }
    }

    // Epilogue: normalize; write bf16 hi/lo into [BT, H*D] for the proj GEMM
    const size_t rowbase = ((size_t)b * TT + qi * 64);
    #pragma unroll
    for (int j = 0; j < 4; j++) {
        float inv = 1.0f / l[j];
        int r = ty * 4 + j;
        size_t off0 = (rowbase + r) * EMB + h * DD;
        #pragma unroll
        for (int i = 0; i < 4; i++) {
            int cc = tx + 16 * i;
            float val = o[j][i] * inv;
            __nv_bfloat16 hv = __float2bfloat16(val);
            g_atthi[off0 + cc] = hv;
            g_attlo[off0 + cc] = __float2bfloat16(val - __bfloat162float(hv));
        }
    }
}

// ---------------------------------------------------------------------------
extern "C" void kernel_launch(void* const* d_in, const int* in_sizes, int n_in,
                              void* d_out, int out_size)
{
    const float* x      = (const float*)d_in[0];
    const float* wq     = (const float*)d_in[1];
    const float* wk     = (const float*)d_in[2];
    const float* wv     = (const float*)d_in[3];
    const float* w_proj = (const float*)d_in[4];
    const float* b_proj = (const float*)d_in[5];
    float* out = (float*)d_out;

    cudaFuncSetAttribute(gemm_tc<0>, cudaFuncAttributeMaxDynamicSharedMemorySize, 2 * ST_SZ);
    cudaFuncSetAttribute(gemm_tc<1>, cudaFuncAttributeMaxDynamicSharedMemorySize, 2 * ST_SZ);

    prep_x<<<(BT * EMB + 255) / 256, 256>>>(x);
    prep_w<<<(3 * HH * DD * EMB + 255) / 256, 256>>>(wq, wk, wv);
    prep_wp<<<(EMB * EMB + 255) / 256, 256>>>(w_proj);

    gemm_tc<0><<<dim3(1152 / 128, BT / 128), 256, 2 * ST_SZ>>>(nullptr, nullptr);
    attn_kernel<<<dim3(TT / 64, BB * HH), 256>>>();
    gemm_tc<1><<<dim3(EMB / 128, BT / 128), 256, 2 * ST_SZ>>>(b_proj, out);
}

// round 4
// speedup vs baseline: 2.8355x; 1.4894x over previous
#include <cuda_runtime.h>
#include <cuda_bf16.h>
#include <cstdint>

#define BB 256
#define TT 256
#define EMB 384
#define HH 6
#define DD 64
#define BT (BB*TT)

// ---------------------------------------------------------------------------
// Scratch (__device__ globals — allocation-free rule)
// ---------------------------------------------------------------------------
__device__ __align__(16) __nv_bfloat16 g_qhi[BB * HH * TT * DD];
__device__ __align__(16) __nv_bfloat16 g_qlo[BB * HH * TT * DD];
__device__ __align__(16) __nv_bfloat16 g_khi[BB * HH * TT * DD];
__device__ __align__(16) __nv_bfloat16 g_klo[BB * HH * TT * DD];
__device__ __align__(16) __nv_bfloat16 g_vhi[BB * HH * TT * DD];
__device__ __align__(16) __nv_bfloat16 g_vlo[BB * HH * TT * DD];
__device__ __align__(16) __nv_bfloat16 g_xhi[BT * EMB];
__device__ __align__(16) __nv_bfloat16 g_xlo[BT * EMB];
__device__ __align__(16) __nv_bfloat16 g_wthi[3 * HH * DD * EMB];  // [n=z*384+h*64+d][e]
__device__ __align__(16) __nv_bfloat16 g_wtlo[3 * HH * DD * EMB];
__device__ __align__(16) __nv_bfloat16 g_wphi[EMB * EMB];          // [n][k]
__device__ __align__(16) __nv_bfloat16 g_wplo[EMB * EMB];
__device__ __align__(16) __nv_bfloat16 g_atthi[BT * EMB];
__device__ __align__(16) __nv_bfloat16 g_attlo[BT * EMB];

// ---------------------------------------------------------------------------
// mma.sync / ldmatrix helpers (sm_80-era; base compute_103-safe)
// ---------------------------------------------------------------------------
__device__ __forceinline__ uint32_t smem_u32(const void* p) {
    uint32_t a;
    asm("{ .reg .u64 t; cvta.to.shared.u64 t, %1; cvt.u32.u64 %0, t; }"
        : "=r"(a) : "l"(p));
    return a;
}
__device__ __forceinline__ void ldm4(uint32_t* r, uint32_t addr) {
    asm volatile("ldmatrix.sync.aligned.m8n8.x4.shared.b16 {%0,%1,%2,%3}, [%4];"
        : "=r"(r[0]), "=r"(r[1]), "=r"(r[2]), "=r"(r[3]) : "r"(addr));
}
__device__ __forceinline__ void ldm4t(uint32_t* r, uint32_t addr) {
    asm volatile("ldmatrix.sync.aligned.m8n8.x4.trans.shared.b16 {%0,%1,%2,%3}, [%4];"
        : "=r"(r[0]), "=r"(r[1]), "=r"(r[2]), "=r"(r[3]) : "r"(addr));
}
__device__ __forceinline__ void mma_bf16(float* c, const uint32_t* a, const uint32_t* b) {
    asm volatile(
        "mma.sync.aligned.m16n8k16.row.col.f32.bf16.bf16.f32 "
        "{%0,%1,%2,%3}, {%4,%5,%6,%7}, {%8,%9}, {%0,%1,%2,%3};"
        : "+f"(c[0]), "+f"(c[1]), "+f"(c[2]), "+f"(c[3])
        : "r"(a[0]), "r"(a[1]), "r"(a[2]), "r"(a[3]), "r"(b[0]), "r"(b[1]));
}
// pack: low half = lo, high half = hi (PTX cvt puts first source in upper half)
__device__ __forceinline__ uint32_t pack_bf16x2(float lo, float hi) {
    uint32_t r;
    asm("cvt.rn.bf16x2.f32 %0, %1, %2;" : "=r"(r) : "f"(hi), "f"(lo));
    return r;
}
// residual pack: (lo - bf16(lo), hi - bf16(hi)) given packed hi-parts u
__device__ __forceinline__ uint32_t pack_resid(uint32_t u, float lo, float hi) {
    float flo = __uint_as_float(u << 16);
    float fhi = __uint_as_float(u & 0xffff0000u);
    return pack_bf16x2(lo - flo, hi - fhi);
}

// gemm smem tile: 128 rows x 4 units of 16B. unit swizzle u ^ ((r>>1)&3).
__device__ __forceinline__ uint32_t swz(uint32_t r, uint32_t u) {
    return (r << 6) + ((u ^ ((r >> 1) & 3u)) << 4);
}
// attn smem tile: 128 rows x 8 units of 16B (row = 64 bf16). swizzle u ^ (r&7).
__device__ __forceinline__ uint32_t swz8(uint32_t r, uint32_t u) {
    return (r << 7) + ((u ^ (r & 7u)) << 4);
}

// ---------------------------------------------------------------------------
// Prep kernels: fp32 -> bf16 hi/lo splits (weights transposed to [n][k])
// ---------------------------------------------------------------------------
__global__ void prep_x(const float* __restrict__ x) {
    int i = blockIdx.x * 256 + threadIdx.x;
    if (i < BT * EMB) {
        float v = x[i];
        __nv_bfloat16 h = __float2bfloat16(v);
        g_xhi[i] = h;
        g_xlo[i] = __float2bfloat16(v - __bfloat162float(h));
    }
}
__global__ void prep_w(const float* __restrict__ wq, const float* __restrict__ wk,
                       const float* __restrict__ wv) {
    int i = blockIdx.x * 256 + threadIdx.x;
    if (i >= 3 * HH * DD * EMB) return;
    int e = i % EMB;
    int d = (i / EMB) % DD;
    int h = (i / (EMB * DD)) % HH;
    int z = i / (EMB * DD * HH);
    const float* w = (z == 0) ? wq : (z == 1) ? wk : wv;
    float v = w[(h * EMB + e) * DD + d];
    __nv_bfloat16 hv = __float2bfloat16(v);
    g_wthi[i] = hv;
    g_wtlo[i] = __float2bfloat16(v - __bfloat162float(hv));
}
__global__ void prep_wp(const float* __restrict__ wp) {
    int i = blockIdx.x * 256 + threadIdx.x;
    if (i >= EMB * EMB) return;
    int k = i % EMB;
    int n = i / EMB;
    float v = wp[k * EMB + n];
    __nv_bfloat16 hv = __float2bfloat16(v);
    g_wphi[i] = hv;
    g_wplo[i] = __float2bfloat16(v - __bfloat162float(hv));
}

// ---------------------------------------------------------------------------
// mma.sync GEMM, 3-term bf16 compensation. C[M,N] = A[M,384] x B[384,N].
// MODE 0: qkv — epilogue writes bf16 hi/lo q/k/v (q pre-scaled by 1/8)
// MODE 1: proj — adds bias, writes fp32 out
// ---------------------------------------------------------------------------
#define ST_SZ   32768
#define OFF_AHI 0
#define OFF_ALO 8192
#define OFF_BHI 16384
#define OFF_BLO 24576

template<int MODE>
__global__ __launch_bounds__(256, 2) void gemm_tc(const float* __restrict__ bias,
                                                  float* __restrict__ outp)
{
    extern __shared__ char sm[];
    const uint32_t sb = smem_u32(sm);

    const char* AhiB = (const char*)(MODE == 0 ? g_xhi : g_atthi);
    const char* AloB = (const char*)(MODE == 0 ? g_xlo : g_attlo);
    const char* BhiB = (const char*)(MODE == 0 ? g_wthi : g_wphi);
    const char* BloB = (const char*)(MODE == 0 ? g_wtlo : g_wplo);

    const int tid  = threadIdx.x;
    const int wid  = tid >> 5;
    const int lane = tid & 31;
    const int m0   = blockIdx.y * 128;
    const int n0   = blockIdx.x * 128;

    const int lr = tid >> 2;
    const int lu = tid & 3;

    const int wm = (wid >> 1) * 32;
    const int wn = (wid & 1) * 64;
    const int a_r  = wm + (lane & 15);
    const int a_u0 = (lane >> 4);
    const int b_r  = wn + ((lane >> 4) & 1) * 8 + (lane & 7);
    const int b_u0 = (lane >> 3) & 1;

    float c[2][8][4];
    #pragma unroll
    for (int mt = 0; mt < 2; mt++)
        #pragma unroll
        for (int nt = 0; nt < 8; nt++)
            #pragma unroll
            for (int q = 0; q < 4; q++) c[mt][nt][q] = 0.0f;

    {
        #pragma unroll
        for (int j = 0; j < 2; j++) {
            int r = lr + j * 64;
            size_t ga = (size_t)(m0 + r) * 768 + lu * 16;
            size_t gb = (size_t)(n0 + r) * 768 + lu * 16;
            *(uint4*)(sm + OFF_AHI + swz(r, lu)) = *(const uint4*)(AhiB + ga);
            *(uint4*)(sm + OFF_ALO + swz(r, lu)) = *(const uint4*)(AloB + ga);
            *(uint4*)(sm + OFF_BHI + swz(r, lu)) = *(const uint4*)(BhiB + gb);
            *(uint4*)(sm + OFF_BLO + swz(r, lu)) = *(const uint4*)(BloB + gb);
        }
    }
    __syncthreads();

    int stage = 0;
    for (int kc = 0; kc < 12; kc++) {
        uint4 v[8];
        if (kc < 11) {
            const int ko = (kc + 1) * 64;
            #pragma unroll
            for (int j = 0; j < 2; j++) {
                int r = lr + j * 64;
                size_t ga = (size_t)(m0 + r) * 768 + ko + lu * 16;
                size_t gb = (size_t)(n0 + r) * 768 + ko + lu * 16;
                v[j * 4 + 0] = *(const uint4*)(AhiB + ga);
                v[j * 4 + 1] = *(const uint4*)(AloB + ga);
                v[j * 4 + 2] = *(const uint4*)(BhiB + gb);
                v[j * 4 + 3] = *(const uint4*)(BloB + gb);
            }
        }

        const uint32_t base = sb + stage * ST_SZ;
        #pragma unroll
        for (int ks = 0; ks < 2; ks++) {
            uint32_t ahi[2][4], alo[2][4], bhi[8][2], blo[8][2];
            #pragma unroll
            for (int mt = 0; mt < 2; mt++) {
                uint32_t r = a_r + mt * 16;
                uint32_t u = ks * 2 + a_u0;
                ldm4(ahi[mt], base + OFF_AHI + swz(r, u));
                ldm4(alo[mt], base + OFF_ALO + swz(r, u));
            }
            #pragma unroll
            for (int p = 0; p < 4; p++) {
                uint32_t r = b_r + p * 16;
                uint32_t u = ks * 2 + b_u0;
                uint32_t t4[4];
                ldm4(t4, base + OFF_BHI + swz(r, u));
                bhi[2 * p][0] = t4[0]; bhi[2 * p][1] = t4[1];
                bhi[2 * p + 1][0] = t4[2]; bhi[2 * p + 1][1] = t4[3];
                ldm4(t4, base + OFF_BLO + swz(r, u));
                blo[2 * p][0] = t4[0]; blo[2 * p][1] = t4[1];
                blo[2 * p + 1][0] = t4[2]; blo[2 * p + 1][1] = t4[3];
            }
            #pragma unroll
            for (int mt = 0; mt < 2; mt++)
                #pragma unroll
                for (int nt = 0; nt < 8; nt++) {
                    mma_bf16(c[mt][nt], ahi[mt], bhi[nt]);
                    mma_bf16(c[mt][nt], alo[mt], bhi[nt]);
                    mma_bf16(c[mt][nt], ahi[mt], blo[nt]);
                }
        }

        if (kc < 11) {
            char* dst = sm + (stage ^ 1) * ST_SZ;
            #pragma unroll
            for (int j = 0; j < 2; j++) {
                int r = lr + j * 64;
                *(uint4*)(dst + OFF_AHI + swz(r, lu)) = v[j * 4 + 0];
                *(uint4*)(dst + OFF_ALO + swz(r, lu)) = v[j * 4 + 1];
                *(uint4*)(dst + OFF_BHI + swz(r, lu)) = v[j * 4 + 2];
                *(uint4*)(dst + OFF_BLO + swz(r, lu)) = v[j * 4 + 3];
            }
        }
        __syncthreads();
        stage ^= 1;
    }

    const int row0 = lane >> 2;
    const int col0 = (lane & 3) * 2;

    if (MODE == 0) {
        const int z = n0 / 384;
        const int nloc = n0 % 384;
        const float scl = (z == 0) ? 0.125f : 1.0f;
        __nv_bfloat16* dhi = (z == 0) ? g_qhi : (z == 1) ? g_khi : g_vhi;
        __nv_bfloat16* dlo = (z == 0) ? g_qlo : (z == 1) ? g_klo : g_vlo;
        #pragma unroll
        for (int mt = 0; mt < 2; mt++)
            #pragma unroll
            for (int half = 0; half < 2; half++) {
                int m = m0 + wm + mt * 16 + row0 + half * 8;
                int b = m >> 8, t = m & 255;
                #pragma unroll
                for (int nt = 0; nt < 8; nt++) {
                    int n = nloc + wn + nt * 8 + col0;
                    int h = n >> 6, d = n & 63;
                    size_t idx = (((size_t)b * HH + h) * TT + t) * DD + d;
                    float v0 = c[mt][nt][half * 2] * scl;
                    float v1 = c[mt][nt][half * 2 + 1] * scl;
                    uint32_t hp = pack_bf16x2(v0, v1);
                    *(uint32_t*)(dhi + idx) = hp;
                    *(uint32_t*)(dlo + idx) = pack_resid(hp, v0, v1);
                }
            }
    } else {
        #pragma unroll
        for (int mt = 0; mt < 2; mt++)
            #pragma unroll
            for (int half = 0; half < 2; half++) {
                int m = m0 + wm + mt * 16 + row0 + half * 8;
                #pragma unroll
                for (int nt = 0; nt < 8; nt++) {
                    int n = n0 + wn + nt * 8 + col0;
                    float2 val = make_float2(c[mt][nt][half * 2] + bias[n],
                                             c[mt][nt][half * 2 + 1] + bias[n + 1]);
                    *(float2*)(outp + (size_t)m * EMB + n) = val;
                }
            }
    }
}

// ---------------------------------------------------------------------------
// Tensor-core causal flash attention. CTA = (qtile of 128 rows) x (b*h).
// 8 warps x 16 q rows. kv tiles of 128. 3-term bf16 compensation on S and PV.
// smem: Qhi/Qlo/Khi/Klo/Vhi/Vlo tiles [128][64] bf16 = 96KB.
// ---------------------------------------------------------------------------
#define AQHI 0
#define AQLO 16384
#define AKHI 32768
#define AKLO 49152
#define AVHI 65536
#define AVLO 81920
#define ATT_SMEM 98304

__global__ __launch_bounds__(256) void attn_tc()
{
    extern __shared__ char sm[];
    const uint32_t sb = smem_u32(sm);
    const int qt  = blockIdx.x;
    const int bh  = blockIdx.y;
    const int tid = threadIdx.x;
    const int wid = tid >> 5;
    const int lane = tid & 31;

    const __nv_bfloat16* qhi = g_qhi + ((size_t)bh * TT + qt * 128) * DD;
    const __nv_bfloat16* qlo = g_qlo + ((size_t)bh * TT + qt * 128) * DD;
    const __nv_bfloat16* khi = g_khi + (size_t)bh * TT * DD;
    const __nv_bfloat16* klo = g_klo + (size_t)bh * TT * DD;
    const __nv_bfloat16* vhi = g_vhi + (size_t)bh * TT * DD;
    const __nv_bfloat16* vlo = g_vlo + (size_t)bh * TT * DD;

    // load Q hi/lo (2 arrays x 1024 uint4 units)
    #pragma unroll
    for (int j = 0; j < 8; j++) {
        int idx = tid + 256 * j;
        int arr = idx >> 10;
        int r = (idx >> 3) & 127;
        int u = idx & 7;
        const __nv_bfloat16* src = arr ? qlo : qhi;
        *(uint4*)(sm + (arr ? AQLO : AQHI) + swz8(r, u)) =
            *(const uint4*)(src + (size_t)r * DD + u * 8);
    }
    __syncthreads();

    // Q fragments (4 k-chunks of 16)
    uint32_t qfh[4][4], qfl[4][4];
    {
        int ar = wid * 16 + (lane & 15);
        #pragma unroll
        for (int kc = 0; kc < 4; kc++) {
            int u = kc * 2 + (lane >> 4);
            ldm4(qfh[kc], sb + AQHI + swz8(ar, u));
            ldm4(qfl[kc], sb + AQLO + swz8(ar, u));
        }
    }

    float o[8][4];
    #pragma unroll
    for (int nt = 0; nt < 8; nt++)
        #pragma unroll
        for (int q = 0; q < 4; q++) o[nt][q] = 0.0f;
    float mx[2] = {-1e30f, -1e30f};
    float lsum[2] = {0.0f, 0.0f};

    for (int kt = 0; kt <= qt; kt++) {
        __syncthreads();
        // load K/V tile hi/lo (4 arrays x 1024 units)
        #pragma unroll
        for (int j = 0; j < 16; j++) {
            int idx = tid + 256 * j;
            int arr = idx >> 10;
            int r = (idx >> 3) & 127;
            int u = idx & 7;
            const __nv_bfloat16* src = (arr == 0) ? khi : (arr == 1) ? klo
                                      : (arr == 2) ? vhi : vlo;
            *(uint4*)(sm + AKHI + arr * 16384 + swz8(r, u)) =
                *(const uint4*)(src + ((size_t)kt * 128 + r) * DD + u * 8);
        }
        __syncthreads();

        // S = Q K^T  (16 x 128 per warp)
        float s[16][4];
        #pragma unroll
        for (int nt = 0; nt < 16; nt++)
            #pragma unroll
            for (int q = 0; q < 4; q++) s[nt][q] = 0.0f;

        #pragma unroll
        for (int np = 0; np < 8; np++) {
            int br = np * 16 + ((lane >> 4) & 1) * 8 + (lane & 7);
            #pragma unroll
            for (int kc = 0; kc < 4; kc++) {
                int u = kc * 2 + ((lane >> 3) & 1);
                uint32_t th[4], tl[4];
                ldm4(th, sb + AKHI + swz8(br, u));
                ldm4(tl, sb + AKLO + swz8(br, u));
                uint32_t b0h[2] = {th[0], th[1]}, b1h[2] = {th[2], th[3]};
                uint32_t b0l[2] = {tl[0], tl[1]}, b1l[2] = {tl[2], tl[3]};
                mma_bf16(s[2 * np], qfh[kc], b0h);
                mma_bf16(s[2 * np], qfl[kc], b0h);
                mma_bf16(s[2 * np], qfh[kc], b0l);
                mma_bf16(s[2 * np + 1], qfh[kc], b1h);
                mma_bf16(s[2 * np + 1], qfl[kc], b1h);
                mma_bf16(s[2 * np + 1], qfh[kc], b1l);
            }
        }

        // causal mask on diagonal tile
        if (kt == qt) {
            #pragma unroll
            for (int nt = 0; nt < 16; nt++)
                #pragma unroll
                for (int q = 0; q < 4; q++) {
                    int col = nt * 8 + (lane & 3) * 2 + (q & 1);
                    int row = wid * 16 + (lane >> 2) + (q >> 1) * 8;
                    if (col > row) s[nt][q] = -1e30f;
                }
        }

        // online softmax (two row-halves per lane)
        float al[2];
        #pragma unroll
        for (int hf = 0; hf < 2; hf++) {
            float rm = -1e30f;
            #pragma unroll
            for (int nt = 0; nt < 16; nt++)
                rm = fmaxf(rm, fmaxf(s[nt][hf * 2], s[nt][hf * 2 + 1]));
            rm = fmaxf(rm, __shfl_xor_sync(0xffffffffu, rm, 1));
            rm = fmaxf(rm, __shfl_xor_sync(0xffffffffu, rm, 2));
            float mn = fmaxf(mx[hf], rm);
            al[hf] = __expf(mx[hf] - mn);
            mx[hf] = mn;
            float ps = 0.0f;
            #pragma unroll
            for (int nt = 0; nt < 16; nt++) {
                s[nt][hf * 2]     = __expf(s[nt][hf * 2] - mn);
                s[nt][hf * 2 + 1] = __expf(s[nt][hf * 2 + 1] - mn);
                ps += s[nt][hf * 2] + s[nt][hf * 2 + 1];
            }
            ps += __shfl_xor_sync(0xffffffffu, ps, 1);
            ps += __shfl_xor_sync(0xffffffffu, ps, 2);
            lsum[hf] = lsum[hf] * al[hf] + ps;
        }
        #pragma unroll
        for (int nt = 0; nt < 8; nt++) {
            o[nt][0] *= al[0]; o[nt][1] *= al[0];
            o[nt][2] *= al[1]; o[nt][3] *= al[1];
        }

        // O += P V  (P hi/lo built in registers; V via trans ldmatrix)
        #pragma unroll
        for (int kc = 0; kc < 8; kc++) {
            uint32_t ah[4], alo4[4];
            ah[0] = pack_bf16x2(s[2 * kc][0], s[2 * kc][1]);
            ah[1] = pack_bf16x2(s[2 * kc][2], s[2 * kc][3]);
            ah[2] = pack_bf16x2(s[2 * kc + 1][0], s[2 * kc + 1][1]);
            ah[3] = pack_bf16x2(s[2 * kc + 1][2], s[2 * kc + 1][3]);
            alo4[0] = pack_resid(ah[0], s[2 * kc][0], s[2 * kc][1]);
            alo4[1] = pack_resid(ah[1], s[2 * kc][2], s[2 * kc][3]);
            alo4[2] = pack_resid(ah[2], s[2 * kc + 1][0], s[2 * kc + 1][1]);
            alo4[3] = pack_resid(ah[3], s[2 * kc + 1][2], s[2 * kc + 1][3]);

            int vr = kc * 16 + ((lane >> 3) & 1) * 8 + (lane & 7);
            #pragma unroll
            for (int ntp = 0; ntp < 4; ntp++) {
                int u = ntp * 2 + (lane >> 4);
                uint32_t th[4], tl[4];
                ldm4t(th, sb + AVHI + swz8(vr, u));
                ldm4t(tl, sb + AVLO + swz8(vr, u));
                uint32_t b0h[2] = {th[0], th[1]}, b1h[2] = {th[2], th[3]};
                uint32_t b0l[2] = {tl[0], tl[1]}, b1l[2] = {tl[2], tl[3]};
                mma_bf16(o[2 * ntp], ah, b0h);
                mma_bf16(o[2 * ntp], alo4, b0h);
                mma_bf16(o[2 * ntp], ah, b0l);
                mma_bf16(o[2 * ntp + 1], ah, b1h);
                mma_bf16(o[2 * ntp + 1], alo4, b1h);
                mma_bf16(o[2 * ntp + 1], ah, b1l);
            }
        }
    }

    // epilogue: normalize, write bf16 hi/lo att rows [BT][EMB]
    const int b = bh / HH, h = bh % HH;
    #pragma unroll
    for (int hf = 0; hf < 2; hf++) {
        float inv = 1.0f / lsum[hf];
        int t = qt * 128 + wid * 16 + (lane >> 2) + hf * 8;
        size_t rowb = ((size_t)b * TT + t) * EMB + h * 64 + (lane & 3) * 2;
        #pragma unroll
        for (int nt = 0; nt < 8; nt++) {
            float v0 = o[nt][hf * 2] * inv;
            float v1 = o[nt][hf * 2 + 1] * inv;
            uint32_t hp = pack_bf16x2(v0, v1);
            *(uint32_t*)(g_atthi + rowb + nt * 8) = hp;
            *(uint32_t*)(g_attlo + rowb + nt * 8) = pack_resid(hp, v0, v1);
        }
    }
}

// ---------------------------------------------------------------------------
extern "C" void kernel_launch(void* const* d_in, const int* in_sizes, int n_in,
                              void* d_out, int out_size)
{
    const float* x      = (const float*)d_in[0];
    const float* wq     = (const float*)d_in[1];
    const float* wk     = (const float*)d_in[2];
    const float* wv     = (const float*)d_in[3];
    const float* w_proj = (const float*)d_in[4];
    const float* b_proj = (const float*)d_in[5];
    float* out = (float*)d_out;

    cudaFuncSetAttribute(gemm_tc<0>, cudaFuncAttributeMaxDynamicSharedMemorySize, 2 * ST_SZ);
    cudaFuncSetAttribute(gemm_tc<1>, cudaFuncAttributeMaxDynamicSharedMemorySize, 2 * ST_SZ);
    cudaFuncSetAttribute(attn_tc, cudaFuncAttributeMaxDynamicSharedMemorySize, ATT_SMEM);

    prep_x<<<(BT * EMB + 255) / 256, 256>>>(x);
    prep_w<<<(3 * HH * DD * EMB + 255) / 256, 256>>>(wq, wk, wv);
    prep_wp<<<(EMB * EMB + 255) / 256, 256>>>(w_proj);

    gemm_tc<0><<<dim3(1152 / 128, BT / 128), 256, 2 * ST_SZ>>>(nullptr, nullptr);
    attn_tc<<<dim3(TT / 128, BB * HH), 256, ATT_SMEM>>>();
    gemm_tc<1><<<dim3(EMB / 128, BT / 128), 256, 2 * ST_SZ>>>(b_proj, out);
}